// round 15
// baseline (speedup 1.0000x reference)
#include <cuda_runtime.h>
#include <cstdint>

// Shapes: L=16, N=128, C=10, D=13, H=128, HID=64, F=88
#define DINL __device__ __forceinline__

// ------------------------- device scratch -------------------------
__device__ __align__(16) float g_h1[4096 * 128];   // LSTM1 final hidden
__device__ __align__(16) float g_lo[2048 * 64];    // lo pre-BN
__device__ __align__(16) float g_part[128 * 64];   // BN1 partial sums
__device__ __align__(16) float g_part2[128 * 64];  // BN1 partial sumsq
__device__ __align__(16) float g_Wcat[256 * 640];  // [Wlh|Wrh] repacked
__device__ __align__(16) float g_bb[5 * 128];      // blh+brh combined
__device__ float g_base[15 * 128];                 // per-step base vectors (a=0)
__device__ __align__(16) float g_h[2][128 * 128];  // tree h state (ping-pong)
__device__ __align__(16) float g_c[2][128 * 128];  // tree c state (ping-pong)
__device__ __align__(16) float g_P2[2][128 * 640]; // tree projection k-partials
__device__ unsigned int g_bar_count;               // grid barrier (self-restoring 0)
__device__ unsigned int g_bar_gen;

// ------------------------- helpers -------------------------
DINL float sigf(float x) { return __fdividef(1.f, 1.f + __expf(-x)); }
DINL float tanh_(float x) { return 2.f * sigf(2.f * x) - 1.f; }
DINL void fma2(unsigned long long& a, unsigned long long b, unsigned long long c) {
    asm("fma.rn.f32x2 %0, %1, %2, %0;" : "+l"(a) : "l"(b), "l"(c));
}
DINL unsigned long long dup2(float x) {
    unsigned long long r;
    asm("mov.b64 %0, {%1, %1};" : "=l"(r) : "f"(x));
    return r;
}
DINL float2 unp2(unsigned long long v) {
    float2 f;
    asm("mov.b64 {%0, %1}, %2;" : "=f"(f.x), "=f"(f.y) : "l"(v));
    return f;
}
DINL void cpasync16(uint32_t dst, const void* src) {
    asm volatile("cp.async.ca.shared.global [%0], [%1], 16;" :: "r"(dst), "l"(src) : "memory");
}
DINL void cp_commit() { asm volatile("cp.async.commit_group;" ::: "memory"); }
DINL void cp_wait1() { asm volatile("cp.async.wait_group 1;" ::: "memory"); }
DINL void cp_wait0() { asm volatile("cp.async.wait_group 0;" ::: "memory"); }

// Software grid barrier (round-11 proven form). Leaves g_bar_count == 0.
DINL void grid_barrier(unsigned int nb) {
    __syncthreads();
    if (threadIdx.x == 0) {
        unsigned int gen;
        asm volatile("ld.acquire.gpu.u32 %0, [%1];"
                     : "=r"(gen) : "l"(&g_bar_gen) : "memory");
        unsigned int old;
        asm volatile("atom.add.release.gpu.u32 %0, [%1], 1;"
                     : "=r"(old) : "l"(&g_bar_count) : "memory");
        if (old == nb - 1) {
            asm volatile("st.relaxed.gpu.u32 [%0], %1;"
                         :: "l"(&g_bar_count), "r"(0u) : "memory");
            asm volatile("st.release.gpu.u32 [%0], %1;"
                         :: "l"(&g_bar_gen), "r"(gen + 1u) : "memory");
        } else {
            unsigned int cur;
            do {
                asm volatile("ld.acquire.gpu.u32 %0, [%1];"
                             : "=r"(cur) : "l"(&g_bar_gen) : "memory");
            } while (cur == gen);
        }
    }
    __syncthreads();
}

// ---------------------------------------------------------------------------
// K1: LSTM1 (+ fused Wcat repack + bb combine prologue).  (unchanged R14)
// ---------------------------------------------------------------------------
DINL void stage_tile3(uint32_t ws_addr, const float* Whh, int tile, int buf, int tid) {
    const char* src = (const char*)Whh + (size_t)tile * 32768 + tid * 16;
    uint32_t dst = ws_addr + buf * 32768 + tid * 16;
#pragma unroll
    for (int p = 0; p < 4; p++)
        cpasync16(dst + p * 8192, src + p * 8192);
}

__global__ void __launch_bounds__(512) lstm1_kernel(
    const float* __restrict__ cond1, const float* __restrict__ cond2,
    const float* __restrict__ Wih, const float* __restrict__ Whh,
    const float* __restrict__ b1,
    const float* __restrict__ Wlh, const float* __restrict__ Wrh,
    const float* __restrict__ blh, const float* __restrict__ brh)
{
    extern __shared__ float smem[];
    float (*z)[144] = (float (*)[144])smem;                 // 4608
    float* wihs = smem + 4608;                              // 6656
    float* ws   = smem + 11264;                             // 24576 (3 x 8192)
    float (*gbF)[132] = (float (*)[132])(smem + 35840);
    float (*gbG)[132] = (float (*)[132])(smem + 40064);
    float (*gbO)[132] = (float (*)[132])(smem + 44288);
    float (*gbC)[132] = (float (*)[132])(smem + 48512);     // ends 52736
    uint32_t wih_addr = (uint32_t)__cvta_generic_to_shared(wihs);
    uint32_t ws_addr  = (uint32_t)__cvta_generic_to_shared(ws);

    const int tid = threadIdx.x, warp = tid >> 5, lane = tid & 31;
    const int g4 = warp >> 2;
    const int lr0 = (warp & 3) * 8;
    const int brow0 = blockIdx.x * 32;

    for (int i = tid; i < 1664; i += 512)
        cpasync16(wih_addr + i * 16, (const char*)Wih + i * 16);
    cp_commit();
    stage_tile3(ws_addr, Whh, 0, 0, tid); cp_commit();
    stage_tile3(ws_addr, Whh, 1, 1, tid); cp_commit();

    {
        int i0 = blockIdx.x * 1280;
#pragma unroll
        for (int it = 0; it < 3; it++) {
            int i = i0 + it * 512 + tid;
            if (it * 512 + tid < 1280) {
                int h = i / 640, col = i - h * 640;
                int gg = col >> 7, k = col & 127;
                g_Wcat[i] = (h < 128) ? Wlh[gg * 16384 + h * 128 + k]
                                      : Wrh[gg * 16384 + (h - 128) * 128 + k];
            }
        }
        if (blockIdx.x == 0 && tid < 640) g_bb[tid] = blh[tid] + brh[tid];
    }

    for (int i = tid; i < 4096; i += 512) z[i >> 7][i & 127] = 0.f;
    for (int i = tid; i < 4224; i += 512) (&gbC[0][0])[i] = 0.f;

    const float* src[8];
#pragma unroll
    for (int r = 0; r < 8; r++) {
        int gr = brow0 + lr0 + r;
        src[r] = (gr < 2048) ? (cond1 + (size_t)gr * 130)
                             : (cond2 + (size_t)(gr - 2048) * 130);
    }
    unsigned long long bias0, bias1;
    {
        ulonglong2 bb = *(const ulonglong2*)(b1 + g4 * 128 + lane * 4);
        bias0 = bb.x; bias1 = bb.y;
    }

    for (int t = 0; t < 10; t++) {
        if (g4 == 0) {
            for (int idx = lane; idx < 104; idx += 32) {
                int r = idx / 13, c = idx - r * 13;
                z[lr0 + r][128 + c] = src[r][t * 13 + c];
            }
        }
        unsigned long long acc[8][2];
#pragma unroll
        for (int r = 0; r < 8; r++) { acc[r][0] = bias0; acc[r][1] = bias1; }

        for (int kt = 0; kt < 8; kt++) {
            cp_wait1();
            __syncthreads();
            const ulonglong2* W = (const ulonglong2*)(ws + ((t * 8 + kt) % 3) * 8192);
#pragma unroll
            for (int kk4 = 0; kk4 < 4; kk4++) {
                float4 a4[8];
#pragma unroll
                for (int r = 0; r < 8; r++)
                    a4[r] = *(const float4*)&z[lr0 + r][kt * 16 + kk4 * 4];
#pragma unroll
                for (int q = 0; q < 4; q++) {
                    ulonglong2 w = W[(kk4 * 4 + q) * 128 + g4 * 32 + lane];
#pragma unroll
                    for (int r = 0; r < 8; r++) {
                        float zv = (q == 0) ? a4[r].x : (q == 1) ? a4[r].y
                                 : (q == 2) ? a4[r].z : a4[r].w;
                        unsigned long long a = dup2(zv);
                        fma2(acc[r][0], a, w.x);
                        fma2(acc[r][1], a, w.y);
                    }
                }
            }
            stage_tile3(ws_addr, Whh, (kt + 2) & 7, (t * 8 + kt + 2) % 3, tid);
            cp_commit();
        }

        {
            const ulonglong2* Wx = (const ulonglong2*)wihs;
#pragma unroll 4
            for (int k = 0; k < 13; k++) {
                ulonglong2 w = Wx[k * 128 + g4 * 32 + lane];
#pragma unroll
                for (int r = 0; r < 8; r++) {
                    unsigned long long a = dup2(z[lr0 + r][128 + k]);
                    fma2(acc[r][0], a, w.x);
                    fma2(acc[r][1], a, w.y);
                }
            }
        }

        if (g4 == 1) {
#pragma unroll
            for (int r = 0; r < 8; r++)
                *(ulonglong2*)&gbF[lr0 + r][lane * 4] = make_ulonglong2(acc[r][0], acc[r][1]);
        } else if (g4 == 2) {
#pragma unroll
            for (int r = 0; r < 8; r++)
                *(ulonglong2*)&gbG[lr0 + r][lane * 4] = make_ulonglong2(acc[r][0], acc[r][1]);
        } else if (g4 == 3) {
#pragma unroll
            for (int r = 0; r < 8; r++)
                *(ulonglong2*)&gbO[lr0 + r][lane * 4] = make_ulonglong2(acc[r][0], acc[r][1]);
        }
        __syncthreads();

        if (g4 == 0) {
#pragma unroll
            for (int r = 0; r < 8; r++) {
                ulonglong2 fu = *(const ulonglong2*)&gbF[lr0 + r][lane * 4];
                ulonglong2 gu = *(const ulonglong2*)&gbG[lr0 + r][lane * 4];
                ulonglong2 ou = *(const ulonglong2*)&gbO[lr0 + r][lane * 4];
                float4 cold = *(const float4*)&gbC[lr0 + r][lane * 4];
                float2 i01 = unp2(acc[r][0]), i23 = unp2(acc[r][1]);
                float2 f01 = unp2(fu.x), f23 = unp2(fu.y);
                float2 G01 = unp2(gu.x), G23 = unp2(gu.y);
                float2 o01 = unp2(ou.x), o23 = unp2(ou.y);
                float iv[4] = {i01.x, i01.y, i23.x, i23.y};
                float fv[4] = {f01.x, f01.y, f23.x, f23.y};
                float gv[4] = {G01.x, G01.y, G23.x, G23.y};
                float ov[4] = {o01.x, o01.y, o23.x, o23.y};
                float cv[4] = {cold.x, cold.y, cold.z, cold.w};
                float hv[4], cn[4];
#pragma unroll
                for (int q = 0; q < 4; q++) {
                    float c = sigf(fv[q]) * cv[q] + sigf(iv[q]) * tanh_(gv[q]);
                    cn[q] = c;
                    hv[q] = sigf(ov[q]) * tanh_(c);
                }
                *(float4*)&gbC[lr0 + r][lane * 4] = make_float4(cn[0], cn[1], cn[2], cn[3]);
                *(float4*)&z[lr0 + r][lane * 4]  = make_float4(hv[0], hv[1], hv[2], hv[3]);
            }
        }
    }

    cp_wait0();
    __syncthreads();
    for (int i = tid; i < 4096; i += 512)
        g_h1[(size_t)(brow0 + (i >> 7)) * 128 + (i & 127)] = z[i >> 7][i & 127];
}

// ---------------------------------------------------------------------------
// K2: lo (unchanged R14, Wc staged in dynamic smem)
// smem (floats): Wcs 8192 | ha 2048 | hb 2048 | red 256 | red2 256 = 12800 f.
// ---------------------------------------------------------------------------
__global__ void __launch_bounds__(256) lo_kernel(const float* __restrict__ Wc,
                                                 const float* __restrict__ bc)
{
    extern __shared__ float losm[];
    float* Wcs = losm;
    float (*ha)[128] = (float (*)[128])(losm + 8192);
    float (*hb)[128] = (float (*)[128])(losm + 8192 + 2048);
    float* red  = losm + 12288;
    float* red2 = losm + 12544;
    uint32_t wcs_addr = (uint32_t)__cvta_generic_to_shared(Wcs);

    int tid = threadIdx.x, r0 = blockIdx.x * 16;
    for (int i = tid; i < 2048; i += 256)
        cpasync16(wcs_addr + i * 16, (const char*)Wc + i * 16);
    cp_commit();

    for (int i = tid; i < 16 * 128; i += 256) {
        int r = i >> 7, h = i & 127;
        ha[r][h] = g_h1[(size_t)(r0 + r) * 128 + h];
        hb[r][h] = g_h1[(size_t)(2048 + r0 + r) * 128 + h];
    }
    cp_wait0();
    __syncthreads();

    int j = tid & 63;
    float ps = 0.f, ps2 = 0.f;
#pragma unroll
    for (int rg = 0; rg < 4; rg++) {
        int r = (tid >> 6) + rg * 4;
        float s1 = bc[j], s2 = s1;
#pragma unroll 4
        for (int h = 0; h < 128; h++) {
            float w = Wcs[h * 64 + j];
            s1 += ha[r][h] * w;
            s2 += hb[r][h] * w;
        }
        float v = 0.5f * (fmaxf(s1, 0.f) + fmaxf(s2, 0.f));
        g_lo[(size_t)(r0 + r) * 64 + j] = v;
        ps += v; ps2 += v * v;
    }
    red[tid] = ps; red2[tid] = ps2;
    __syncthreads();
    if (tid < 64) {
        for (int p = 1; p < 4; p++) { ps += red[tid + 64 * p]; ps2 += red2[tid + 64 * p]; }
        g_part[blockIdx.x * 64 + tid] = ps;
        g_part2[blockIdx.x * 64 + tid] = ps2;
    }
}

// ---------------------------------------------------------------------------
// K3: FUSED prep + tree scan + tail.  grid (8,5,2)=80 blocks, 256 threads.
// Phase A (prep): BN1 finalize per block; 2 units/block (LSTM2 rows / base).
// Phase B (tree): round-11 core, pointwise spread over all 80 blocks.
// Phase C (tail): block 0 only, after final barrier.
// smem (floats): Wsm 16384 | A[16][132] 2112 = 18496 f = 73984 B.
// Prep scratch overlays A; tail scratch overlays Wsm.
// ---------------------------------------------------------------------------
__global__ void __launch_bounds__(256) tree_fused_kernel(
    const int* __restrict__ mapping,
    const float* __restrict__ ops, const float* __restrict__ ext,
    const float* __restrict__ card, const float* __restrict__ Wih2,
    const float* __restrict__ b2, const float* __restrict__ Win,
    const float* __restrict__ bin_,
    const float* __restrict__ g1, const float* __restrict__ be1,
    const float* __restrict__ g2, const float* __restrict__ be2,
    const float* __restrict__ Wt1, const float* __restrict__ bt1,
    const float* __restrict__ g3, const float* __restrict__ be3,
    const float* __restrict__ Wt2, const float* __restrict__ bt2,
    const float* __restrict__ Wo, const float* __restrict__ bo,
    float* __restrict__ out)
{
    const unsigned int NB = 80;
    extern __shared__ float smem[];
    float* Wsm = smem;                       // [k(128)][c(128)]
    float (*A)[132] = (float (*)[132])(smem + 16384);
    uint32_t wsm_addr = (uint32_t)__cvta_generic_to_shared(Wsm);

    const int tid = threadIdx.x;
    const int bx = blockIdx.x, g = blockIdx.y, kz = blockIdx.z;
    const int bid = (kz * 5 + g) * 8 + bx;   // 0..79

    // ---------------- Phase A: prep (2 units per block) ----------------
    {
        float* Ares = smem + 16384;          // overlay region (2112 floats)
        float (*xx)[88] = (float (*)[88])Ares;       // 176
        float* sc1s = Ares + 176;                    // 64
        float* sh1s = Ares + 240;                    // 64
        float* r1   = Ares + 304;                    // 256
        float* r2   = Ares + 560;                    // 256

        // BN1 finalize (all 256 threads, deterministic)
        {
            int col = tid & 63, part = tid >> 6;
            float s = 0.f, s2 = 0.f;
            for (int q = part; q < 128; q += 4) {
                s += g_part[q * 64 + col];
                s2 += g_part2[q * 64 + col];
            }
            r1[tid] = s; r2[tid] = s2;
            __syncthreads();
            if (tid < 64) {
                for (int p = 1; p < 4; p++) { s += r1[tid + 64 * p]; s2 += r2[tid + 64 * p]; }
                float m = s * (1.f / 2048.f);
                float v = s2 * (1.f / 2048.f) - m * m;
                float sc = g1[tid] * rsqrtf(v + 1e-5f);
                sc1s[tid] = sc;
                sh1s[tid] = be1[tid] - m * sc;
            }
            __syncthreads();
        }

        int half = tid >> 7, k = tid & 127;
        int u = bid * 2 + half;              // unit 0..159 (valid < 143)
        if (u < 143) {
            int row = (u < 128) ? (15 * 128 + u) : ((u - 128) * 128 + 0);
            if (k < 15)      xx[half][k] = ops[row * 15 + k];
            else if (k < 22) xx[half][k] = ext[row * 7 + (k - 15)];
            else if (k < 24) xx[half][k] = card[row * 2 + (k - 22)];
            else if (k < 88) xx[half][k] = g_lo[(size_t)row * 64 + (k - 24)] * sc1s[k - 24] + sh1s[k - 24];
        }
        __syncthreads();

        if (u < 143) {
            if (u < 128) {
                float gi = b2[k], gg = b2[256 + k], go = b2[384 + k];
#pragma unroll 8
                for (int j = 0; j < 88; j++) {
                    float xv = xx[half][j];
                    const float* w = Wih2 + j * 512;
                    gi += xv * w[k];
                    gg += xv * w[256 + k];
                    go += xv * w[384 + k];
                }
                float c = sigf(gi) * tanh_(gg);  // sig(f)*c_prev = 0
                float h = sigf(go) * tanh_(c);
                g_h[0][u * 128 + k] = h;
                g_c[0][u * 128 + k] = c;
            } else {
                int l = u - 128;
                float s = bin_[k];
#pragma unroll 8
                for (int j = 0; j < 88; j++) s += xx[half][j] * Win[j * 128 + k];
                g_base[(14 - l) * 128 + k] = s;
            }
        }
        // stage tree W slice while arriving at barrier
        for (int i = tid; i < 4096; i += 256)
            cpasync16(wsm_addr + i * 16,
                      g_Wcat + (size_t)(kz * 128 + (i >> 5)) * 640 + g * 128 + (i & 31) * 4);
        cp_commit();
    }

    grid_barrier(NB);   // g_h[0], g_c[0], g_base visible

    // ---------------- Phase B: tree scan ----------------
    const int warp = tid >> 5, lane = tid & 31;
    const int rg = warp >> 1;
    const int ch = warp & 1;
    const unsigned long long* Wul = (const unsigned long long*)Wsm;
    cp_wait0();
    __syncthreads();

    for (int s = 0; s < 15; s++) {
        int lvl = 14 - s, p = s & 1;
        const float* __restrict__ hprev = g_h[p];

        for (int i = tid; i < 2048; i += 256) {
            int r = i >> 7, hcol = i & 127;
            int n = bx * 16 + r;
            int mp = mapping[(lvl * 128 + n) * 2 + kz];
            A[r][hcol] = (mp > 0) ? hprev[(mp - 1) * 128 + hcol] : 0.f;
        }
        __syncthreads();

        unsigned long long acc[4] = {0ull, 0ull, 0ull, 0ull};
#pragma unroll 4
        for (int kk4 = 0; kk4 < 32; kk4++) {
            float4 a4[4];
#pragma unroll
            for (int r = 0; r < 4; r++)
                a4[r] = *(const float4*)&A[rg * 4 + r][kk4 * 4];
#pragma unroll
            for (int qq = 0; qq < 4; qq++) {
                unsigned long long w = Wul[(kk4 * 4 + qq) * 64 + ch * 32 + lane];
#pragma unroll
                for (int r = 0; r < 4; r++) {
                    float av = (qq == 0) ? a4[r].x : (qq == 1) ? a4[r].y
                             : (qq == 2) ? a4[r].z : a4[r].w;
                    fma2(acc[r], dup2(av), w);
                }
            }
        }
#pragma unroll
        for (int r = 0; r < 4; r++) {
            int n = bx * 16 + rg * 4 + r;
            *(unsigned long long*)(g_P2[kz] + (size_t)n * 640 + g * 128 + ch * 64 + lane * 2)
                = acc[r];
        }

        grid_barrier(NB);

        // pointwise: 16384 elems spread over ALL 80 blocks (205 each)
        {
            int idx = bid * 205 + tid;
            if (tid < 205 && idx < 16384) {
                int n = idx >> 7, k = idx & 127;
                int mp0 = mapping[(lvl * 128 + n) * 2 + 0];
                int mp1 = mapping[(lvl * 128 + n) * 2 + 1];
                float lc = (mp0 > 0) ? g_c[p][(mp0 - 1) * 128 + k] : 0.f;
                float rc = (mp1 > 0) ? g_c[p][(mp1 - 1) * 128 + k] : 0.f;
                float bse = g_base[s * 128 + k];
                const float* P0 = g_P2[0] + (size_t)n * 640;
                const float* P1 = g_P2[1] + (size_t)n * 640;
                float pre[5];
#pragma unroll
                for (int qq = 0; qq < 5; qq++)
                    pre[qq] = bse + P0[qq * 128 + k] + P1[qq * 128 + k] + g_bb[qq * 128 + k];
                float ii = sigf(pre[0]), lf = sigf(pre[1]), rf = sigf(pre[2]);
                float u = tanh_(pre[3]), o = sigf(pre[4]);
                float c = ii * u + lf * lc + rf * rc;
                g_c[1 - p][n * 128 + k] = c;
                g_h[1 - p][n * 128 + k] = o * tanh_(c);
            }
        }

        grid_barrier(NB);
    }

    // ---------------- Phase C: tail (block 0 only) ----------------
    if (bid == 0) {
        float* t1s  = Wsm;          // 8192
        float* sc   = Wsm + 8192;   // 128
        float* sh   = Wsm + 8320;   // 128
        float* red  = Wsm + 8448;   // 256
        float* red2 = Wsm + 8704;   // 256

        // BN2 stats over g_h[1] (128x128)
        {
            int col = tid & 127, part = tid >> 7;
            float s = 0.f, s2 = 0.f;
            for (int r = part; r < 128; r += 2) {
                float v = g_h[1][r * 128 + col];
                s += v; s2 += v * v;
            }
            red[tid] = s; red2[tid] = s2;
            __syncthreads();
            if (tid < 128) {
                s = red[tid] + red[tid + 128];
                s2 = red2[tid] + red2[tid + 128];
                float m = s * (1.f / 128.f);
                float v = s2 * (1.f / 128.f) - m * m;
                float scl = g2[tid] * rsqrtf(v + 1e-5f);
                sc[tid] = scl;
                sh[tid] = be2[tid] - m * scl;
            }
            __syncthreads();
        }

        // t1 = relu(bn2(h) @ Wt1 + bt1)
        for (int o = tid; o < 8192; o += 256) {
            int n = o >> 6, j = o & 63;
            float acc = bt1[j];
#pragma unroll 4
            for (int h = 0; h < 128; h++)
                acc += (g_h[1][n * 128 + h] * sc[h] + sh[h]) * Wt1[h * 64 + j];
            t1s[o] = fmaxf(acc, 0.f);
        }
        __syncthreads();

        // BN3 stats over t1s (128x64)
        {
            int col = tid & 63, part = tid >> 6;
            float s = 0.f, s2 = 0.f;
            for (int r = part; r < 128; r += 4) {
                float v = t1s[r * 64 + col];
                s += v; s2 += v * v;
            }
            red[tid] = s; red2[tid] = s2;
            __syncthreads();
            if (tid < 64) {
                for (int p = 1; p < 4; p++) { s += red[tid + 64 * p]; s2 += red2[tid + 64 * p]; }
                float m = s * (1.f / 128.f);
                float v = s2 * (1.f / 128.f) - m * m;
                float scl = g3[tid] * rsqrtf(v + 1e-5f);
                sc[tid] = scl;
                sh[tid] = be3[tid] - m * scl;
            }
            __syncthreads();
        }

        // t2 = relu(bn3(t1)@Wt2+bt2); out = sigmoid(t2@Wo+bo)
        if (tid < 128) {
            int n = tid;
            float tn[64];
#pragma unroll
            for (int i = 0; i < 64; i++) tn[i] = t1s[n * 64 + i] * sc[i] + sh[i];
            float a = bo[0];
            for (int j = 0; j < 64; j++) {
                float s = bt2[j];
#pragma unroll
                for (int i = 0; i < 64; i++) s += tn[i] * Wt2[i * 64 + j];
                a += fmaxf(s, 0.f) * Wo[j];
            }
            out[n] = sigf(a);
        }
    }
}

// ---------------------------------------------------------------------------
extern "C" void kernel_launch(void* const* d_in, const int* in_sizes, int n_in,
                              void* d_out, int out_size)
{
    const float* operators = (const float*)d_in[0];
    const float* extra     = (const float*)d_in[1];
    const float* card      = (const float*)d_in[2];
    const float* cond1     = (const float*)d_in[3];
    const float* cond2     = (const float*)d_in[4];
    const int*   mapping   = (const int*)  d_in[5];
    const float* Wih1      = (const float*)d_in[6];
    const float* Whh1      = (const float*)d_in[7];
    const float* b1        = (const float*)d_in[8];
    const float* Wc        = (const float*)d_in[9];
    const float* bc        = (const float*)d_in[10];
    const float* g1        = (const float*)d_in[11];
    const float* be1       = (const float*)d_in[12];
    const float* Wih2      = (const float*)d_in[13];
    // d_in[14] = Whh2: unused (single step from zero state)
    const float* b2        = (const float*)d_in[15];
    const float* Win       = (const float*)d_in[16];
    const float* bin_      = (const float*)d_in[17];
    const float* Wlh       = (const float*)d_in[18];
    const float* blh       = (const float*)d_in[19];
    const float* Wrh       = (const float*)d_in[20];
    const float* brh       = (const float*)d_in[21];
    const float* g2        = (const float*)d_in[22];
    const float* be2       = (const float*)d_in[23];
    const float* Wt1       = (const float*)d_in[24];
    const float* bt1       = (const float*)d_in[25];
    const float* g3        = (const float*)d_in[26];
    const float* be3       = (const float*)d_in[27];
    const float* Wt2       = (const float*)d_in[28];
    const float* bt2       = (const float*)d_in[29];
    const float* Wo        = (const float*)d_in[30];
    const float* bo        = (const float*)d_in[31];
    float* out = (float*)d_out;

    const int LSTM1_SMEM = 52736 * 4;   // 210944 B
    const int TREE_SMEM  = 18496 * 4;   // 73984 B
    const int LO_SMEM    = 12800 * 4;   // 51200 B
    cudaFuncSetAttribute(lstm1_kernel,
                         cudaFuncAttributeMaxDynamicSharedMemorySize, LSTM1_SMEM);
    cudaFuncSetAttribute(tree_fused_kernel,
                         cudaFuncAttributeMaxDynamicSharedMemorySize, TREE_SMEM);
    cudaFuncSetAttribute(lo_kernel,
                         cudaFuncAttributeMaxDynamicSharedMemorySize, LO_SMEM);

    // 3 launches
    lstm1_kernel<<<128, 512, LSTM1_SMEM>>>(cond1, cond2, Wih1, Whh1, b1,
                                           Wlh, Wrh, blh, brh);
    lo_kernel<<<128, 256, LO_SMEM>>>(Wc, bc);
    tree_fused_kernel<<<dim3(8, 5, 2), 256, TREE_SMEM>>>(
        mapping, operators, extra, card, Wih2, b2, Win, bin_, g1, be1,
        g2, be2, Wt1, bt1, g3, be3, Wt2, bt2, Wo, bo, out);
}

// round 16
// speedup vs baseline: 1.0655x; 1.0655x over previous
#include <cuda_runtime.h>
#include <cstdint>

// Shapes: L=16, N=128, C=10, D=13, H=128, HID=64, F=88
#define DINL __device__ __forceinline__

// ------------------------- device scratch -------------------------
__device__ __align__(16) float g_h1[4096 * 128];   // LSTM1 final hidden
__device__ __align__(16) float g_lo[2048 * 64];    // lo pre-BN
__device__ __align__(16) float g_part[128 * 64];   // BN1 partial sums
__device__ __align__(16) float g_part2[128 * 64];  // BN1 partial sumsq
__device__ __align__(16) float g_Wcat[256 * 640];  // [Wlh|Wrh] repacked
__device__ __align__(16) float g_bb[5 * 128];      // blh+brh combined
__device__ float g_base[15 * 128];                 // per-step base vectors (a=0)
__device__ __align__(16) float g_h[2][128 * 128];  // tree h state (ping-pong)
__device__ __align__(16) float g_c[2][128 * 128];  // tree c state (ping-pong)
__device__ __align__(16) float g_P2[2][128 * 640]; // tree projection k-partials
__device__ unsigned int g_bar_count;               // grid barrier (self-restoring 0)
__device__ unsigned int g_bar_gen;

// ------------------------- helpers -------------------------
DINL float sigf(float x) { return __fdividef(1.f, 1.f + __expf(-x)); }
DINL float tanh_(float x) { return 2.f * sigf(2.f * x) - 1.f; }
DINL void fma2(unsigned long long& a, unsigned long long b, unsigned long long c) {
    asm("fma.rn.f32x2 %0, %1, %2, %0;" : "+l"(a) : "l"(b), "l"(c));
}
DINL unsigned long long dup2(float x) {
    unsigned long long r;
    asm("mov.b64 %0, {%1, %1};" : "=l"(r) : "f"(x));
    return r;
}
DINL float2 unp2(unsigned long long v) {
    float2 f;
    asm("mov.b64 {%0, %1}, %2;" : "=f"(f.x), "=f"(f.y) : "l"(v));
    return f;
}
DINL void cpasync16(uint32_t dst, const void* src) {
    asm volatile("cp.async.ca.shared.global [%0], [%1], 16;" :: "r"(dst), "l"(src) : "memory");
}
DINL void cp_commit() { asm volatile("cp.async.commit_group;" ::: "memory"); }
DINL void cp_wait1() { asm volatile("cp.async.wait_group 1;" ::: "memory"); }
DINL void cp_wait0() { asm volatile("cp.async.wait_group 0;" ::: "memory"); }

// Software grid barrier (round-11 proven form). Leaves g_bar_count == 0.
DINL void grid_barrier(unsigned int nb) {
    __syncthreads();
    if (threadIdx.x == 0) {
        unsigned int gen;
        asm volatile("ld.acquire.gpu.u32 %0, [%1];"
                     : "=r"(gen) : "l"(&g_bar_gen) : "memory");
        unsigned int old;
        asm volatile("atom.add.release.gpu.u32 %0, [%1], 1;"
                     : "=r"(old) : "l"(&g_bar_count) : "memory");
        if (old == nb - 1) {
            asm volatile("st.relaxed.gpu.u32 [%0], %1;"
                         :: "l"(&g_bar_count), "r"(0u) : "memory");
            asm volatile("st.release.gpu.u32 [%0], %1;"
                         :: "l"(&g_bar_gen), "r"(gen + 1u) : "memory");
        } else {
            unsigned int cur;
            do {
                asm volatile("ld.acquire.gpu.u32 %0, [%1];"
                             : "=r"(cur) : "l"(&g_bar_gen) : "memory");
            } while (cur == gen);
        }
    }
    __syncthreads();
}

// ---------------------------------------------------------------------------
// K1: LSTM1 (+ fused Wcat repack + bb combine prologue).
// Per-gate warp split: block 512 = 16 warps; warp w: gate g4=w>>2, rows
// lr0=(w&3)*8.  3-buffer cp.async pipeline, one __syncthreads per 16-k tile.
// smem (floats): z[32][144] 4608 | wihs 6656 | ws 3*8192 | gbF/G/O/C 4*4224
//   = 52736 floats = 210944 B.
// ---------------------------------------------------------------------------
DINL void stage_tile3(uint32_t ws_addr, const float* Whh, int tile, int buf, int tid) {
    const char* src = (const char*)Whh + (size_t)tile * 32768 + tid * 16;
    uint32_t dst = ws_addr + buf * 32768 + tid * 16;
#pragma unroll
    for (int p = 0; p < 4; p++)
        cpasync16(dst + p * 8192, src + p * 8192);
}

__global__ void __launch_bounds__(512) lstm1_kernel(
    const float* __restrict__ cond1, const float* __restrict__ cond2,
    const float* __restrict__ Wih, const float* __restrict__ Whh,
    const float* __restrict__ b1,
    const float* __restrict__ Wlh, const float* __restrict__ Wrh,
    const float* __restrict__ blh, const float* __restrict__ brh)
{
    extern __shared__ float smem[];
    float (*z)[144] = (float (*)[144])smem;                 // 4608
    float* wihs = smem + 4608;                              // 6656
    float* ws   = smem + 11264;                             // 24576 (3 x 8192)
    float (*gbF)[132] = (float (*)[132])(smem + 35840);
    float (*gbG)[132] = (float (*)[132])(smem + 40064);
    float (*gbO)[132] = (float (*)[132])(smem + 44288);
    float (*gbC)[132] = (float (*)[132])(smem + 48512);     // ends 52736
    uint32_t wih_addr = (uint32_t)__cvta_generic_to_shared(wihs);
    uint32_t ws_addr  = (uint32_t)__cvta_generic_to_shared(ws);

    const int tid = threadIdx.x, warp = tid >> 5, lane = tid & 31;
    const int g4 = warp >> 2;          // gate index 0=i,1=f,2=g,3=o
    const int lr0 = (warp & 3) * 8;    // 8 rows per warp
    const int brow0 = blockIdx.x * 32;

    // stage Wih (group A), Whh tiles 0,1 (groups B,C)
    for (int i = tid; i < 1664; i += 512)
        cpasync16(wih_addr + i * 16, (const char*)Wih + i * 16);
    cp_commit();
    stage_tile3(ws_addr, Whh, 0, 0, tid); cp_commit();
    stage_tile3(ws_addr, Whh, 1, 1, tid); cp_commit();

    // fused prologue: Wcat repack slice + bb combine (under cp.async latency)
    {
        int i0 = blockIdx.x * 1280;
#pragma unroll
        for (int it = 0; it < 3; it++) {
            int i = i0 + it * 512 + tid;
            if (it * 512 + tid < 1280) {
                int h = i / 640, col = i - h * 640;
                int gg = col >> 7, k = col & 127;
                g_Wcat[i] = (h < 128) ? Wlh[gg * 16384 + h * 128 + k]
                                      : Wrh[gg * 16384 + (h - 128) * 128 + k];
            }
        }
        if (blockIdx.x == 0 && tid < 640) g_bb[tid] = blh[tid] + brh[tid];
    }

    // zero h region and c state
    for (int i = tid; i < 4096; i += 512) z[i >> 7][i & 127] = 0.f;
    for (int i = tid; i < 4224; i += 512) (&gbC[0][0])[i] = 0.f;

    const float* src[8];
#pragma unroll
    for (int r = 0; r < 8; r++) {
        int gr = brow0 + lr0 + r;
        src[r] = (gr < 2048) ? (cond1 + (size_t)gr * 130)
                             : (cond2 + (size_t)(gr - 2048) * 130);
    }
    unsigned long long bias0, bias1;
    {
        ulonglong2 bb = *(const ulonglong2*)(b1 + g4 * 128 + lane * 4);
        bias0 = bb.x; bias1 = bb.y;
    }

    for (int t = 0; t < 10; t++) {
        if (g4 == 0) {  // i-warps own x loads for their 8 rows
            for (int idx = lane; idx < 104; idx += 32) {
                int r = idx / 13, c = idx - r * 13;
                z[lr0 + r][128 + c] = src[r][t * 13 + c];
            }
        }
        unsigned long long acc[8][2];
#pragma unroll
        for (int r = 0; r < 8; r++) { acc[r][0] = bias0; acc[r][1] = bias1; }

        // h @ Whh: 8 tiles of 16 k, 3-buffer pipeline, 1 sync per tile
        for (int kt = 0; kt < 8; kt++) {
            cp_wait1();
            __syncthreads();   // tile kt staged & visible; h/x visible at kt==0
            const ulonglong2* W = (const ulonglong2*)(ws + ((t * 8 + kt) % 3) * 8192);
#pragma unroll
            for (int kk4 = 0; kk4 < 4; kk4++) {
                float4 a4[8];
#pragma unroll
                for (int r = 0; r < 8; r++)
                    a4[r] = *(const float4*)&z[lr0 + r][kt * 16 + kk4 * 4];
#pragma unroll
                for (int q = 0; q < 4; q++) {
                    ulonglong2 w = W[(kk4 * 4 + q) * 128 + g4 * 32 + lane];
#pragma unroll
                    for (int r = 0; r < 8; r++) {
                        float zv = (q == 0) ? a4[r].x : (q == 1) ? a4[r].y
                                 : (q == 2) ? a4[r].z : a4[r].w;
                        unsigned long long a = dup2(zv);
                        fma2(acc[r][0], a, w.x);
                        fma2(acc[r][1], a, w.y);
                    }
                }
            }
            stage_tile3(ws_addr, Whh, (kt + 2) & 7, (t * 8 + kt + 2) % 3, tid);
            cp_commit();
        }

        // x @ Wih from resident smem
        {
            const ulonglong2* Wx = (const ulonglong2*)wihs;
#pragma unroll 4
            for (int k = 0; k < 13; k++) {
                ulonglong2 w = Wx[k * 128 + g4 * 32 + lane];
#pragma unroll
                for (int r = 0; r < 8; r++) {
                    unsigned long long a = dup2(z[lr0 + r][128 + k]);
                    fma2(acc[r][0], a, w.x);
                    fma2(acc[r][1], a, w.y);
                }
            }
        }

        // publish f,g,o pre-activations
        if (g4 == 1) {
#pragma unroll
            for (int r = 0; r < 8; r++)
                *(ulonglong2*)&gbF[lr0 + r][lane * 4] = make_ulonglong2(acc[r][0], acc[r][1]);
        } else if (g4 == 2) {
#pragma unroll
            for (int r = 0; r < 8; r++)
                *(ulonglong2*)&gbG[lr0 + r][lane * 4] = make_ulonglong2(acc[r][0], acc[r][1]);
        } else if (g4 == 3) {
#pragma unroll
            for (int r = 0; r < 8; r++)
                *(ulonglong2*)&gbO[lr0 + r][lane * 4] = make_ulonglong2(acc[r][0], acc[r][1]);
        }
        __syncthreads();

        if (g4 == 0) {  // cell update, c state in smem
#pragma unroll
            for (int r = 0; r < 8; r++) {
                ulonglong2 fu = *(const ulonglong2*)&gbF[lr0 + r][lane * 4];
                ulonglong2 gu = *(const ulonglong2*)&gbG[lr0 + r][lane * 4];
                ulonglong2 ou = *(const ulonglong2*)&gbO[lr0 + r][lane * 4];
                float4 cold = *(const float4*)&gbC[lr0 + r][lane * 4];
                float2 i01 = unp2(acc[r][0]), i23 = unp2(acc[r][1]);
                float2 f01 = unp2(fu.x), f23 = unp2(fu.y);
                float2 G01 = unp2(gu.x), G23 = unp2(gu.y);
                float2 o01 = unp2(ou.x), o23 = unp2(ou.y);
                float iv[4] = {i01.x, i01.y, i23.x, i23.y};
                float fv[4] = {f01.x, f01.y, f23.x, f23.y};
                float gv[4] = {G01.x, G01.y, G23.x, G23.y};
                float ov[4] = {o01.x, o01.y, o23.x, o23.y};
                float cv[4] = {cold.x, cold.y, cold.z, cold.w};
                float hv[4], cn[4];
#pragma unroll
                for (int q = 0; q < 4; q++) {
                    float c = sigf(fv[q]) * cv[q] + sigf(iv[q]) * tanh_(gv[q]);
                    cn[q] = c;
                    hv[q] = sigf(ov[q]) * tanh_(c);
                }
                *(float4*)&gbC[lr0 + r][lane * 4] = make_float4(cn[0], cn[1], cn[2], cn[3]);
                *(float4*)&z[lr0 + r][lane * 4]  = make_float4(hv[0], hv[1], hv[2], hv[3]);
            }
        }
        // visibility of new h/x: next iteration's kt==0 __syncthreads
    }

    cp_wait0();       // retire stray prefetch groups
    __syncthreads();
    for (int i = tid; i < 4096; i += 512)
        g_h1[(size_t)(brow0 + (i >> 7)) * 128 + (i & 127)] = z[i >> 7][i & 127];
}

// ---------------------------------------------------------------------------
// K2: lo = 0.5*(relu(h1@Wc+bc)+relu(h2@Wc+bc)) (2048x64), 16 rows/block,
// plus deterministic per-block BN1 partial sums.  Wc staged in dynamic smem.
// smem (floats): Wcs 8192 | ha 2048 | hb 2048 | red 256 | red2 256 = 12800 f.
// ---------------------------------------------------------------------------
__global__ void __launch_bounds__(256) lo_kernel(const float* __restrict__ Wc,
                                                 const float* __restrict__ bc)
{
    extern __shared__ float losm[];
    float* Wcs = losm;                       // 8192
    float (*ha)[128] = (float (*)[128])(losm + 8192);
    float (*hb)[128] = (float (*)[128])(losm + 8192 + 2048);
    float* red  = losm + 12288;
    float* red2 = losm + 12544;
    uint32_t wcs_addr = (uint32_t)__cvta_generic_to_shared(Wcs);

    int tid = threadIdx.x, r0 = blockIdx.x * 16;
    // stage Wc (8192 floats = 2048 x 16B)
    for (int i = tid; i < 2048; i += 256)
        cpasync16(wcs_addr + i * 16, (const char*)Wc + i * 16);
    cp_commit();

    for (int i = tid; i < 16 * 128; i += 256) {
        int r = i >> 7, h = i & 127;
        ha[r][h] = g_h1[(size_t)(r0 + r) * 128 + h];
        hb[r][h] = g_h1[(size_t)(2048 + r0 + r) * 128 + h];
    }
    cp_wait0();
    __syncthreads();

    int j = tid & 63;
    float ps = 0.f, ps2 = 0.f;
#pragma unroll
    for (int rg = 0; rg < 4; rg++) {
        int r = (tid >> 6) + rg * 4;
        float s1 = bc[j], s2 = s1;
#pragma unroll 4
        for (int h = 0; h < 128; h++) {
            float w = Wcs[h * 64 + j];
            s1 += ha[r][h] * w;
            s2 += hb[r][h] * w;
        }
        float v = 0.5f * (fmaxf(s1, 0.f) + fmaxf(s2, 0.f));
        g_lo[(size_t)(r0 + r) * 64 + j] = v;
        ps += v; ps2 += v * v;
    }
    red[tid] = ps; red2[tid] = ps2;
    __syncthreads();
    if (tid < 64) {
        for (int p = 1; p < 4; p++) { ps += red[tid + 64 * p]; ps2 += red2[tid + 64 * p]; }
        g_part[blockIdx.x * 64 + tid] = ps;
        g_part2[blockIdx.x * 64 + tid] = ps2;
    }
}

// ---------------------------------------------------------------------------
// K3: prep = redundant BN1 finalize (per block, deterministic) + LSTM2 single
// step from zero state (blocks 0..127) + base vectors (blocks 128..142).
// ---------------------------------------------------------------------------
__global__ void __launch_bounds__(128) prep_kernel(
    const float* __restrict__ ops, const float* __restrict__ ext,
    const float* __restrict__ card, const float* __restrict__ Wih2,
    const float* __restrict__ b2, const float* __restrict__ Win,
    const float* __restrict__ bin_,
    const float* __restrict__ g1, const float* __restrict__ be1)
{
    __shared__ float x[88];
    __shared__ float sc1s[64], sh1s[64];
    __shared__ float r1[128], r2[128];
    int b = blockIdx.x, k = threadIdx.x;

    // BN1 finalize (every block, identical deterministic result)
    {
        int col = k & 63, part = k >> 6;
        float s = 0.f, s2 = 0.f;
        for (int q = part; q < 128; q += 2) {
            s += g_part[q * 64 + col];
            s2 += g_part2[q * 64 + col];
        }
        r1[k] = s; r2[k] = s2;
        __syncthreads();
        if (k < 64) {
            s = r1[k] + r1[k + 64];
            s2 = r2[k] + r2[k + 64];
            float m = s * (1.f / 2048.f);
            float v = s2 * (1.f / 2048.f) - m * m;
            float sc = g1[k] * rsqrtf(v + 1e-5f);
            sc1s[k] = sc;
            sh1s[k] = be1[k] - m * sc;
        }
        __syncthreads();
    }

    int row = (b < 128) ? (15 * 128 + b) : ((b - 128) * 128 + 0);
    if (k < 15)      x[k] = ops[row * 15 + k];
    else if (k < 22) x[k] = ext[row * 7 + (k - 15)];
    else if (k < 24) x[k] = card[row * 2 + (k - 22)];
    else if (k < 88) x[k] = g_lo[(size_t)row * 64 + (k - 24)] * sc1s[k - 24] + sh1s[k - 24];
    __syncthreads();

    if (b < 128) {
        float gi = b2[k], gg = b2[256 + k], go = b2[384 + k];
        for (int j = 0; j < 88; j++) {
            float xv = x[j];
            const float* w = Wih2 + j * 512;
            gi += xv * w[k];
            gg += xv * w[256 + k];
            go += xv * w[384 + k];
        }
        float c = sigf(gi) * tanh_(gg);  // sig(f)*c_prev = 0
        float h = sigf(go) * tanh_(c);
        g_h[0][b * 128 + k] = h;
        g_c[0][b * 128 + k] = c;
    } else {
        int l = b - 128;
        float s = bin_[k];
        for (int j = 0; j < 88; j++) s += x[j] * Win[j * 128 + k];
        g_base[(14 - l) * 128 + k] = s;
    }
}

// ---------------------------------------------------------------------------
// K4: fused tree scan — 15 steps, persistent. grid (8,5,2)=80 blocks, 256 thr.
// Block (bx, g, kz): GEMM partial over k-half kz for gate g, rows bx*16..+16.
// The two k-partials are summed in the pointwise (no intra-block reduction).
// Pointwise spread over ALL 80 blocks (205 elems/block).
// smem (floats): Wsm 128x128 = 16384 | A[16][132] 2112  = 18496 f = 73984 B.
// ---------------------------------------------------------------------------
__global__ void __launch_bounds__(256) tree_kernel(const int* __restrict__ mapping)
{
    const unsigned int NB = 80;
    extern __shared__ float smem[];
    float* Wsm = smem;                       // [k(128)][c(128)]
    float (*A)[132] = (float (*)[132])(smem + 16384);
    uint32_t wsm_addr = (uint32_t)__cvta_generic_to_shared(Wsm);

    const int tid = threadIdx.x;
    const int bx = blockIdx.x, g = blockIdx.y, kz = blockIdx.z;
    const int bid = (kz * 5 + g) * 8 + bx;   // 0..79

    // stage W slice: Wsm[k][c] = g_Wcat[(kz*128+k)*640 + g*128 + c]
    for (int i = tid; i < 4096; i += 256)
        cpasync16(wsm_addr + i * 16,
                  g_Wcat + (size_t)(kz * 128 + (i >> 5)) * 640 + g * 128 + (i & 31) * 4);
    cp_commit();

    const int warp = tid >> 5, lane = tid & 31;
    const int rg = warp >> 1;                // row group 0..3 -> rows rg*4..+4
    const int ch = warp & 1;                 // col half
    const unsigned long long* Wul = (const unsigned long long*)Wsm;

    cp_wait0();
    __syncthreads();

    for (int s = 0; s < 15; s++) {
        int lvl = 14 - s, p = s & 1;
        const float* __restrict__ hprev = g_h[p];

        // gather A: this block's 16 rows, k-half kz (kz==0 -> lh, kz==1 -> rh)
        for (int i = tid; i < 2048; i += 256) {
            int r = i >> 7, hcol = i & 127;
            int n = bx * 16 + r;
            int mp = mapping[(lvl * 128 + n) * 2 + kz];
            A[r][hcol] = (mp > 0) ? hprev[(mp - 1) * 128 + hcol] : 0.f;
        }
        __syncthreads();

        // GEMM partial: rows rg*4..+4, cols ch*64 + lane*2 (+1), k 0..127
        unsigned long long acc[4] = {0ull, 0ull, 0ull, 0ull};
#pragma unroll 4
        for (int kk4 = 0; kk4 < 32; kk4++) {
            float4 a4[4];
#pragma unroll
            for (int r = 0; r < 4; r++)
                a4[r] = *(const float4*)&A[rg * 4 + r][kk4 * 4];
#pragma unroll
            for (int qq = 0; qq < 4; qq++) {
                unsigned long long w = Wul[(kk4 * 4 + qq) * 64 + ch * 32 + lane];
#pragma unroll
                for (int r = 0; r < 4; r++) {
                    float av = (qq == 0) ? a4[r].x : (qq == 1) ? a4[r].y
                             : (qq == 2) ? a4[r].z : a4[r].w;
                    fma2(acc[r], dup2(av), w);
                }
            }
        }

        // store partials
#pragma unroll
        for (int r = 0; r < 4; r++) {
            int n = bx * 16 + rg * 4 + r;
            *(unsigned long long*)(g_P2[kz] + (size_t)n * 640 + g * 128 + ch * 64 + lane * 2)
                = acc[r];
        }

        grid_barrier(NB);

        // pointwise: 16384 elems spread over ALL 80 blocks (205 each)
        {
            int idx = bid * 205 + tid;
            if (tid < 205 && idx < 16384) {
                int n = idx >> 7, k = idx & 127;
                int mp0 = mapping[(lvl * 128 + n) * 2 + 0];
                int mp1 = mapping[(lvl * 128 + n) * 2 + 1];
                float lc = (mp0 > 0) ? g_c[p][(mp0 - 1) * 128 + k] : 0.f;
                float rc = (mp1 > 0) ? g_c[p][(mp1 - 1) * 128 + k] : 0.f;
                float bse = g_base[s * 128 + k];
                const float* P0 = g_P2[0] + (size_t)n * 640;
                const float* P1 = g_P2[1] + (size_t)n * 640;
                float pre[5];
#pragma unroll
                for (int qq = 0; qq < 5; qq++)
                    pre[qq] = bse + P0[qq * 128 + k] + P1[qq * 128 + k] + g_bb[qq * 128 + k];
                float ii = sigf(pre[0]), lf = sigf(pre[1]), rf = sigf(pre[2]);
                float u = tanh_(pre[3]), o = sigf(pre[4]);
                float c = ii * u + lf * lc + rf * rc;
                g_c[1 - p][n * 128 + k] = c;
                g_h[1 - p][n * 128 + k] = o * tanh_(c);
            }
        }

        grid_barrier(NB);
    }
}

// ---------------------------------------------------------------------------
// K5: fused tail: BN2 -> t1 -> BN3 -> t2 -> sigmoid output.  One block, 256.
// ---------------------------------------------------------------------------
__global__ void __launch_bounds__(256) tail_kernel(
    const float* __restrict__ g2, const float* __restrict__ be2,
    const float* __restrict__ Wt1, const float* __restrict__ bt1,
    const float* __restrict__ g3, const float* __restrict__ be3,
    const float* __restrict__ Wt2, const float* __restrict__ bt2,
    const float* __restrict__ Wo, const float* __restrict__ bo,
    float* __restrict__ out)
{
    __shared__ float t1s[128 * 64];  // 32KB
    __shared__ float sc[128], sh[128];
    __shared__ float red[256], red2[256];
    int tid = threadIdx.x;

    // BN2 stats over g_h[1] (128x128)
    {
        int col = tid & 127, part = tid >> 7;
        float s = 0.f, s2 = 0.f;
        for (int r = part; r < 128; r += 2) {
            float v = g_h[1][r * 128 + col];
            s += v; s2 += v * v;
        }
        red[tid] = s; red2[tid] = s2;
        __syncthreads();
        if (tid < 128) {
            s = red[tid] + red[tid + 128];
            s2 = red2[tid] + red2[tid + 128];
            float m = s * (1.f / 128.f);
            float v = s2 * (1.f / 128.f) - m * m;
            float scl = g2[tid] * rsqrtf(v + 1e-5f);
            sc[tid] = scl;
            sh[tid] = be2[tid] - m * scl;
        }
        __syncthreads();
    }

    // t1 = relu(bn2(h) @ Wt1 + bt1)  (128x64)
    for (int o = tid; o < 8192; o += 256) {
        int n = o >> 6, j = o & 63;
        float acc = bt1[j];
        for (int h = 0; h < 128; h++)
            acc += (g_h[1][n * 128 + h] * sc[h] + sh[h]) * Wt1[h * 64 + j];
        t1s[o] = fmaxf(acc, 0.f);
    }
    __syncthreads();

    // BN3 stats over t1s (128x64)
    {
        int col = tid & 63, part = tid >> 6;
        float s = 0.f, s2 = 0.f;
        for (int r = part; r < 128; r += 4) {
            float v = t1s[r * 64 + col];
            s += v; s2 += v * v;
        }
        red[tid] = s; red2[tid] = s2;
        __syncthreads();
        if (tid < 64) {
            for (int p = 1; p < 4; p++) { s += red[tid + 64 * p]; s2 += red2[tid + 64 * p]; }
            float m = s * (1.f / 128.f);
            float v = s2 * (1.f / 128.f) - m * m;
            float scl = g3[tid] * rsqrtf(v + 1e-5f);
            sc[tid] = scl;
            sh[tid] = be3[tid] - m * scl;
        }
        __syncthreads();
    }

    // t2 = relu(bn3(t1)@Wt2+bt2); out = sigmoid(t2@Wo+bo)
    if (tid < 128) {
        int n = tid;
        float tn[64];
#pragma unroll
        for (int i = 0; i < 64; i++) tn[i] = t1s[n * 64 + i] * sc[i] + sh[i];
        float a = bo[0];
        for (int j = 0; j < 64; j++) {
            float s = bt2[j];
#pragma unroll
            for (int i = 0; i < 64; i++) s += tn[i] * Wt2[i * 64 + j];
            a += fmaxf(s, 0.f) * Wo[j];
        }
        out[n] = sigf(a);
    }
}

// ---------------------------------------------------------------------------
extern "C" void kernel_launch(void* const* d_in, const int* in_sizes, int n_in,
                              void* d_out, int out_size)
{
    const float* operators = (const float*)d_in[0];
    const float* extra     = (const float*)d_in[1];
    const float* card      = (const float*)d_in[2];
    const float* cond1     = (const float*)d_in[3];
    const float* cond2     = (const float*)d_in[4];
    const int*   mapping   = (const int*)  d_in[5];
    const float* Wih1      = (const float*)d_in[6];
    const float* Whh1      = (const float*)d_in[7];
    const float* b1        = (const float*)d_in[8];
    const float* Wc        = (const float*)d_in[9];
    const float* bc        = (const float*)d_in[10];
    const float* g1        = (const float*)d_in[11];
    const float* be1       = (const float*)d_in[12];
    const float* Wih2      = (const float*)d_in[13];
    // d_in[14] = Whh2: unused (single step from zero state)
    const float* b2        = (const float*)d_in[15];
    const float* Win       = (const float*)d_in[16];
    const float* bin_      = (const float*)d_in[17];
    const float* Wlh       = (const float*)d_in[18];
    const float* blh       = (const float*)d_in[19];
    const float* Wrh       = (const float*)d_in[20];
    const float* brh       = (const float*)d_in[21];
    const float* g2        = (const float*)d_in[22];
    const float* be2       = (const float*)d_in[23];
    const float* Wt1       = (const float*)d_in[24];
    const float* bt1       = (const float*)d_in[25];
    const float* g3        = (const float*)d_in[26];
    const float* be3       = (const float*)d_in[27];
    const float* Wt2       = (const float*)d_in[28];
    const float* bt2       = (const float*)d_in[29];
    const float* Wo        = (const float*)d_in[30];
    const float* bo        = (const float*)d_in[31];
    float* out = (float*)d_out;

    const int LSTM1_SMEM = 52736 * 4;   // 210944 B
    const int TREE_SMEM  = 18496 * 4;   // 73984 B
    const int LO_SMEM    = 12800 * 4;   // 51200 B
    cudaFuncSetAttribute(lstm1_kernel,
                         cudaFuncAttributeMaxDynamicSharedMemorySize, LSTM1_SMEM);
    cudaFuncSetAttribute(tree_kernel,
                         cudaFuncAttributeMaxDynamicSharedMemorySize, TREE_SMEM);
    cudaFuncSetAttribute(lo_kernel,
                         cudaFuncAttributeMaxDynamicSharedMemorySize, LO_SMEM);

    // 5 launches; tree at our idx 3 so ncu (-s 5) profiles it.
    lstm1_kernel<<<128, 512, LSTM1_SMEM>>>(cond1, cond2, Wih1, Whh1, b1,
                                           Wlh, Wrh, blh, brh);
    lo_kernel<<<128, 256, LO_SMEM>>>(Wc, bc);
    prep_kernel<<<143, 128>>>(operators, extra, card, Wih2, b2, Win, bin_, g1, be1);
    tree_kernel<<<dim3(8, 5, 2), 256, TREE_SMEM>>>(mapping);
    tail_kernel<<<1, 256>>>(g2, be2, Wt1, bt1, g3, be3, Wt2, bt2, Wo, bo, out);
}

// round 17
// speedup vs baseline: 1.0879x; 1.0210x over previous
#include <cuda_runtime.h>
#include <cstdint>

// Shapes: L=16, N=128, C=10, D=13, H=128, HID=64, F=88
#define DINL __device__ __forceinline__

// ------------------------- device scratch -------------------------
__device__ __align__(16) float g_h1[4096 * 128];   // LSTM1 final hidden
__device__ __align__(16) float g_lo[2048 * 64];    // lo pre-BN
__device__ __align__(16) float g_part[128 * 64];   // BN1 partial sums
__device__ __align__(16) float g_part2[128 * 64];  // BN1 partial sumsq
__device__ __align__(16) float g_Wcat[256 * 640];  // [Wlh|Wrh] repacked
__device__ __align__(16) float g_bb[5 * 128];      // blh+brh combined
__device__ float g_base[15 * 128];                 // per-step base vectors (a=0)
__device__ __align__(16) float g_h[2][128 * 128];  // tree h state (ping-pong)
__device__ __align__(16) float g_c[2][128 * 128];  // tree c state (ping-pong)
__device__ __align__(16) float g_P2[2][128 * 640]; // tree projection k-partials
__device__ unsigned int g_bar_count;               // grid barrier (self-restoring 0)
__device__ unsigned int g_bar_gen;

// ------------------------- helpers -------------------------
DINL float sigf(float x) { return __fdividef(1.f, 1.f + __expf(-x)); }
DINL float tanh_(float x) { return 2.f * sigf(2.f * x) - 1.f; }
DINL void fma2(unsigned long long& a, unsigned long long b, unsigned long long c) {
    asm("fma.rn.f32x2 %0, %1, %2, %0;" : "+l"(a) : "l"(b), "l"(c));
}
DINL unsigned long long dup2(float x) {
    unsigned long long r;
    asm("mov.b64 %0, {%1, %1};" : "=l"(r) : "f"(x));
    return r;
}
DINL float2 unp2(unsigned long long v) {
    float2 f;
    asm("mov.b64 {%0, %1}, %2;" : "=f"(f.x), "=f"(f.y) : "l"(v));
    return f;
}
DINL void cpasync16(uint32_t dst, const void* src) {
    asm volatile("cp.async.ca.shared.global [%0], [%1], 16;" :: "r"(dst), "l"(src) : "memory");
}
DINL void cp_commit() { asm volatile("cp.async.commit_group;" ::: "memory"); }
DINL void cp_wait1() { asm volatile("cp.async.wait_group 1;" ::: "memory"); }
DINL void cp_wait0() { asm volatile("cp.async.wait_group 0;" ::: "memory"); }

// Software grid barrier (round-11 proven form). Leaves g_bar_count == 0.
DINL void grid_barrier(unsigned int nb) {
    __syncthreads();
    if (threadIdx.x == 0) {
        unsigned int gen;
        asm volatile("ld.acquire.gpu.u32 %0, [%1];"
                     : "=r"(gen) : "l"(&g_bar_gen) : "memory");
        unsigned int old;
        asm volatile("atom.add.release.gpu.u32 %0, [%1], 1;"
                     : "=r"(old) : "l"(&g_bar_count) : "memory");
        if (old == nb - 1) {
            asm volatile("st.relaxed.gpu.u32 [%0], %1;"
                         :: "l"(&g_bar_count), "r"(0u) : "memory");
            asm volatile("st.release.gpu.u32 [%0], %1;"
                         :: "l"(&g_bar_gen), "r"(gen + 1u) : "memory");
        } else {
            unsigned int cur;
            do {
                asm volatile("ld.acquire.gpu.u32 %0, [%1];"
                             : "=r"(cur) : "l"(&g_bar_gen) : "memory");
            } while (cur == gen);
        }
    }
    __syncthreads();
}

// ---------------------------------------------------------------------------
// K1: LSTM1 (+ fused Wcat repack + bb combine prologue).
// NEW: 28 rows/block x 148 blocks (full SM coverage; was 32 x 128 with 20
// SMs idle).  Per-gate warp split: block 512 = 16 warps; warp w: gate
// g4=w>>2, rows lr0=(w&3)*7 (7 rows per warp).  3-buffer cp.async pipeline,
// one __syncthreads per 16-k tile.
// smem (floats): z[28][144] 4032 | wihs 6656 | ws 3*8192=24576 |
//   gbF/G/O/C 4*3696=14784  -> total 50048 floats = 200192 B.
// ---------------------------------------------------------------------------
DINL void stage_tile3(uint32_t ws_addr, const float* Whh, int tile, int buf, int tid) {
    const char* src = (const char*)Whh + (size_t)tile * 32768 + tid * 16;
    uint32_t dst = ws_addr + buf * 32768 + tid * 16;
#pragma unroll
    for (int p = 0; p < 4; p++)
        cpasync16(dst + p * 8192, src + p * 8192);
}

__global__ void __launch_bounds__(512) lstm1_kernel(
    const float* __restrict__ cond1, const float* __restrict__ cond2,
    const float* __restrict__ Wih, const float* __restrict__ Whh,
    const float* __restrict__ b1,
    const float* __restrict__ Wlh, const float* __restrict__ Wrh,
    const float* __restrict__ blh, const float* __restrict__ brh)
{
    extern __shared__ float smem[];
    float (*z)[144] = (float (*)[144])smem;                 // 4032
    float* wihs = smem + 4032;                              // 6656
    float* ws   = smem + 10688;                             // 24576 (3 x 8192)
    float (*gbF)[132] = (float (*)[132])(smem + 35264);
    float (*gbG)[132] = (float (*)[132])(smem + 38960);
    float (*gbO)[132] = (float (*)[132])(smem + 42656);
    float (*gbC)[132] = (float (*)[132])(smem + 46352);     // ends 50048
    uint32_t wih_addr = (uint32_t)__cvta_generic_to_shared(wihs);
    uint32_t ws_addr  = (uint32_t)__cvta_generic_to_shared(ws);

    const int tid = threadIdx.x, warp = tid >> 5, lane = tid & 31;
    const int g4 = warp >> 2;          // gate index 0=i,1=f,2=g,3=o
    const int lr0 = (warp & 3) * 7;    // 7 rows per warp
    const int brow0 = blockIdx.x * 28;

    // stage Wih (group A), Whh tiles 0,1 (groups B,C)
    for (int i = tid; i < 1664; i += 512)
        cpasync16(wih_addr + i * 16, (const char*)Wih + i * 16);
    cp_commit();
    stage_tile3(ws_addr, Whh, 0, 0, tid); cp_commit();
    stage_tile3(ws_addr, Whh, 1, 1, tid); cp_commit();

    // fused prologue: Wcat repack slice + bb combine (under cp.async latency)
    {
        int i0 = blockIdx.x * 1108;   // ceil(163840/148)
#pragma unroll
        for (int it = 0; it < 3; it++) {
            int j = it * 512 + tid;
            int i = i0 + j;
            if (j < 1108 && i < 163840) {
                int h = i / 640, col = i - h * 640;
                int gg = col >> 7, k = col & 127;
                g_Wcat[i] = (h < 128) ? Wlh[gg * 16384 + h * 128 + k]
                                      : Wrh[gg * 16384 + (h - 128) * 128 + k];
            }
        }
        if (blockIdx.x == 0 && tid < 640) g_bb[tid] = blh[tid] + brh[tid];
    }

    // zero h region and c state
    for (int i = tid; i < 3584; i += 512) z[i >> 7][i & 127] = 0.f;
    for (int i = tid; i < 3696; i += 512) (&gbC[0][0])[i] = 0.f;

    const float* src[7];
#pragma unroll
    for (int r = 0; r < 7; r++) {
        int gr = brow0 + lr0 + r;
        int grc = (gr < 4096) ? gr : 0;   // clamp: rows >= 4096 never stored
        src[r] = (grc < 2048) ? (cond1 + (size_t)grc * 130)
                              : (cond2 + (size_t)(grc - 2048) * 130);
    }
    unsigned long long bias0, bias1;
    {
        ulonglong2 bb = *(const ulonglong2*)(b1 + g4 * 128 + lane * 4);
        bias0 = bb.x; bias1 = bb.y;
    }

    for (int t = 0; t < 10; t++) {
        if (g4 == 0) {  // i-warps own x loads for their 7 rows (7*13 = 91)
            for (int idx = lane; idx < 91; idx += 32) {
                int r = idx / 13, c = idx - r * 13;
                z[lr0 + r][128 + c] = src[r][t * 13 + c];
            }
        }
        unsigned long long acc[7][2];
#pragma unroll
        for (int r = 0; r < 7; r++) { acc[r][0] = bias0; acc[r][1] = bias1; }

        // h @ Whh: 8 tiles of 16 k, 3-buffer pipeline, 1 sync per tile
        for (int kt = 0; kt < 8; kt++) {
            cp_wait1();
            __syncthreads();   // tile kt staged & visible; h/x visible at kt==0
            const ulonglong2* W = (const ulonglong2*)(ws + ((t * 8 + kt) % 3) * 8192);
#pragma unroll
            for (int kk4 = 0; kk4 < 4; kk4++) {
                float4 a4[7];
#pragma unroll
                for (int r = 0; r < 7; r++)
                    a4[r] = *(const float4*)&z[lr0 + r][kt * 16 + kk4 * 4];
#pragma unroll
                for (int q = 0; q < 4; q++) {
                    ulonglong2 w = W[(kk4 * 4 + q) * 128 + g4 * 32 + lane];
#pragma unroll
                    for (int r = 0; r < 7; r++) {
                        float zv = (q == 0) ? a4[r].x : (q == 1) ? a4[r].y
                                 : (q == 2) ? a4[r].z : a4[r].w;
                        unsigned long long a = dup2(zv);
                        fma2(acc[r][0], a, w.x);
                        fma2(acc[r][1], a, w.y);
                    }
                }
            }
            stage_tile3(ws_addr, Whh, (kt + 2) & 7, (t * 8 + kt + 2) % 3, tid);
            cp_commit();
        }

        // x @ Wih from resident smem
        {
            const ulonglong2* Wx = (const ulonglong2*)wihs;
#pragma unroll 4
            for (int k = 0; k < 13; k++) {
                ulonglong2 w = Wx[k * 128 + g4 * 32 + lane];
#pragma unroll
                for (int r = 0; r < 7; r++) {
                    unsigned long long a = dup2(z[lr0 + r][128 + k]);
                    fma2(acc[r][0], a, w.x);
                    fma2(acc[r][1], a, w.y);
                }
            }
        }

        // publish f,g,o pre-activations
        if (g4 == 1) {
#pragma unroll
            for (int r = 0; r < 7; r++)
                *(ulonglong2*)&gbF[lr0 + r][lane * 4] = make_ulonglong2(acc[r][0], acc[r][1]);
        } else if (g4 == 2) {
#pragma unroll
            for (int r = 0; r < 7; r++)
                *(ulonglong2*)&gbG[lr0 + r][lane * 4] = make_ulonglong2(acc[r][0], acc[r][1]);
        } else if (g4 == 3) {
#pragma unroll
            for (int r = 0; r < 7; r++)
                *(ulonglong2*)&gbO[lr0 + r][lane * 4] = make_ulonglong2(acc[r][0], acc[r][1]);
        }
        __syncthreads();

        if (g4 == 0) {  // cell update, c state in smem
#pragma unroll
            for (int r = 0; r < 7; r++) {
                ulonglong2 fu = *(const ulonglong2*)&gbF[lr0 + r][lane * 4];
                ulonglong2 gu = *(const ulonglong2*)&gbG[lr0 + r][lane * 4];
                ulonglong2 ou = *(const ulonglong2*)&gbO[lr0 + r][lane * 4];
                float4 cold = *(const float4*)&gbC[lr0 + r][lane * 4];
                float2 i01 = unp2(acc[r][0]), i23 = unp2(acc[r][1]);
                float2 f01 = unp2(fu.x), f23 = unp2(fu.y);
                float2 G01 = unp2(gu.x), G23 = unp2(gu.y);
                float2 o01 = unp2(ou.x), o23 = unp2(ou.y);
                float iv[4] = {i01.x, i01.y, i23.x, i23.y};
                float fv[4] = {f01.x, f01.y, f23.x, f23.y};
                float gv[4] = {G01.x, G01.y, G23.x, G23.y};
                float ov[4] = {o01.x, o01.y, o23.x, o23.y};
                float cv[4] = {cold.x, cold.y, cold.z, cold.w};
                float hv[4], cn[4];
#pragma unroll
                for (int q = 0; q < 4; q++) {
                    float c = sigf(fv[q]) * cv[q] + sigf(iv[q]) * tanh_(gv[q]);
                    cn[q] = c;
                    hv[q] = sigf(ov[q]) * tanh_(c);
                }
                *(float4*)&gbC[lr0 + r][lane * 4] = make_float4(cn[0], cn[1], cn[2], cn[3]);
                *(float4*)&z[lr0 + r][lane * 4]  = make_float4(hv[0], hv[1], hv[2], hv[3]);
            }
        }
        // visibility of new h/x: next iteration's kt==0 __syncthreads
    }

    cp_wait0();       // retire stray prefetch groups
    __syncthreads();
    for (int i = tid; i < 3584; i += 512) {
        int row = brow0 + (i >> 7);
        if (row < 4096)
            g_h1[(size_t)row * 128 + (i & 127)] = z[i >> 7][i & 127];
    }
}

// ---------------------------------------------------------------------------
// K2: lo = 0.5*(relu(h1@Wc+bc)+relu(h2@Wc+bc)) (2048x64), 16 rows/block,
// plus deterministic per-block BN1 partial sums.  Wc staged in dynamic smem.
// smem (floats): Wcs 8192 | ha 2048 | hb 2048 | red 256 | red2 256 = 12800 f.
// ---------------------------------------------------------------------------
__global__ void __launch_bounds__(256) lo_kernel(const float* __restrict__ Wc,
                                                 const float* __restrict__ bc)
{
    extern __shared__ float losm[];
    float* Wcs = losm;                       // 8192
    float (*ha)[128] = (float (*)[128])(losm + 8192);
    float (*hb)[128] = (float (*)[128])(losm + 8192 + 2048);
    float* red  = losm + 12288;
    float* red2 = losm + 12544;
    uint32_t wcs_addr = (uint32_t)__cvta_generic_to_shared(Wcs);

    int tid = threadIdx.x, r0 = blockIdx.x * 16;
    // stage Wc (8192 floats = 2048 x 16B)
    for (int i = tid; i < 2048; i += 256)
        cpasync16(wcs_addr + i * 16, (const char*)Wc + i * 16);
    cp_commit();

    for (int i = tid; i < 16 * 128; i += 256) {
        int r = i >> 7, h = i & 127;
        ha[r][h] = g_h1[(size_t)(r0 + r) * 128 + h];
        hb[r][h] = g_h1[(size_t)(2048 + r0 + r) * 128 + h];
    }
    cp_wait0();
    __syncthreads();

    int j = tid & 63;
    float ps = 0.f, ps2 = 0.f;
#pragma unroll
    for (int rg = 0; rg < 4; rg++) {
        int r = (tid >> 6) + rg * 4;
        float s1 = bc[j], s2 = s1;
#pragma unroll 4
        for (int h = 0; h < 128; h++) {
            float w = Wcs[h * 64 + j];
            s1 += ha[r][h] * w;
            s2 += hb[r][h] * w;
        }
        float v = 0.5f * (fmaxf(s1, 0.f) + fmaxf(s2, 0.f));
        g_lo[(size_t)(r0 + r) * 64 + j] = v;
        ps += v; ps2 += v * v;
    }
    red[tid] = ps; red2[tid] = ps2;
    __syncthreads();
    if (tid < 64) {
        for (int p = 1; p < 4; p++) { ps += red[tid + 64 * p]; ps2 += red2[tid + 64 * p]; }
        g_part[blockIdx.x * 64 + tid] = ps;
        g_part2[blockIdx.x * 64 + tid] = ps2;
    }
}

// ---------------------------------------------------------------------------
// K3: prep = redundant BN1 finalize (per block, deterministic) + LSTM2 single
// step from zero state (blocks 0..127) + base vectors (blocks 128..142).
// ---------------------------------------------------------------------------
__global__ void __launch_bounds__(128) prep_kernel(
    const float* __restrict__ ops, const float* __restrict__ ext,
    const float* __restrict__ card, const float* __restrict__ Wih2,
    const float* __restrict__ b2, const float* __restrict__ Win,
    const float* __restrict__ bin_,
    const float* __restrict__ g1, const float* __restrict__ be1)
{
    __shared__ float x[88];
    __shared__ float sc1s[64], sh1s[64];
    __shared__ float r1[128], r2[128];
    int b = blockIdx.x, k = threadIdx.x;

    // BN1 finalize (every block, identical deterministic result)
    {
        int col = k & 63, part = k >> 6;
        float s = 0.f, s2 = 0.f;
        for (int q = part; q < 128; q += 2) {
            s += g_part[q * 64 + col];
            s2 += g_part2[q * 64 + col];
        }
        r1[k] = s; r2[k] = s2;
        __syncthreads();
        if (k < 64) {
            s = r1[k] + r1[k + 64];
            s2 = r2[k] + r2[k + 64];
            float m = s * (1.f / 2048.f);
            float v = s2 * (1.f / 2048.f) - m * m;
            float sc = g1[k] * rsqrtf(v + 1e-5f);
            sc1s[k] = sc;
            sh1s[k] = be1[k] - m * sc;
        }
        __syncthreads();
    }

    int row = (b < 128) ? (15 * 128 + b) : ((b - 128) * 128 + 0);
    if (k < 15)      x[k] = ops[row * 15 + k];
    else if (k < 22) x[k] = ext[row * 7 + (k - 15)];
    else if (k < 24) x[k] = card[row * 2 + (k - 22)];
    else if (k < 88) x[k] = g_lo[(size_t)row * 64 + (k - 24)] * sc1s[k - 24] + sh1s[k - 24];
    __syncthreads();

    if (b < 128) {
        float gi = b2[k], gg = b2[256 + k], go = b2[384 + k];
#pragma unroll 8
        for (int j = 0; j < 88; j++) {
            float xv = x[j];
            const float* w = Wih2 + j * 512;
            gi += xv * w[k];
            gg += xv * w[256 + k];
            go += xv * w[384 + k];
        }
        float c = sigf(gi) * tanh_(gg);  // sig(f)*c_prev = 0
        float h = sigf(go) * tanh_(c);
        g_h[0][b * 128 + k] = h;
        g_c[0][b * 128 + k] = c;
    } else {
        int l = b - 128;
        float s = bin_[k];
#pragma unroll 8
        for (int j = 0; j < 88; j++) s += x[j] * Win[j * 128 + k];
        g_base[(14 - l) * 128 + k] = s;
    }
}

// ---------------------------------------------------------------------------
// K4: fused tree scan — 15 steps, persistent. grid (8,5,2)=80 blocks, 256 thr.
// Block (bx, g, kz): GEMM partial over k-half kz for gate g, rows bx*16..+16.
// The two k-partials are summed in the pointwise (no intra-block reduction).
// Pointwise spread over ALL 80 blocks (205 elems/block).
// smem (floats): Wsm 128x128 = 16384 | A[16][132] 2112  = 18496 f = 73984 B.
// ---------------------------------------------------------------------------
__global__ void __launch_bounds__(256) tree_kernel(const int* __restrict__ mapping)
{
    const unsigned int NB = 80;
    extern __shared__ float smem[];
    float* Wsm = smem;                       // [k(128)][c(128)]
    float (*A)[132] = (float (*)[132])(smem + 16384);
    uint32_t wsm_addr = (uint32_t)__cvta_generic_to_shared(Wsm);

    const int tid = threadIdx.x;
    const int bx = blockIdx.x, g = blockIdx.y, kz = blockIdx.z;
    const int bid = (kz * 5 + g) * 8 + bx;   // 0..79

    // stage W slice: Wsm[k][c] = g_Wcat[(kz*128+k)*640 + g*128 + c]
    for (int i = tid; i < 4096; i += 256)
        cpasync16(wsm_addr + i * 16,
                  g_Wcat + (size_t)(kz * 128 + (i >> 5)) * 640 + g * 128 + (i & 31) * 4);
    cp_commit();

    const int warp = tid >> 5, lane = tid & 31;
    const int rg = warp >> 1;                // row group 0..3 -> rows rg*4..+4
    const int ch = warp & 1;                 // col half
    const unsigned long long* Wul = (const unsigned long long*)Wsm;

    cp_wait0();
    __syncthreads();

    for (int s = 0; s < 15; s++) {
        int lvl = 14 - s, p = s & 1;
        const float* __restrict__ hprev = g_h[p];

        // gather A: this block's 16 rows, k-half kz (kz==0 -> lh, kz==1 -> rh)
        for (int i = tid; i < 2048; i += 256) {
            int r = i >> 7, hcol = i & 127;
            int n = bx * 16 + r;
            int mp = mapping[(lvl * 128 + n) * 2 + kz];
            A[r][hcol] = (mp > 0) ? hprev[(mp - 1) * 128 + hcol] : 0.f;
        }
        __syncthreads();

        // GEMM partial: rows rg*4..+4, cols ch*64 + lane*2 (+1), k 0..127
        unsigned long long acc[4] = {0ull, 0ull, 0ull, 0ull};
#pragma unroll 4
        for (int kk4 = 0; kk4 < 32; kk4++) {
            float4 a4[4];
#pragma unroll
            for (int r = 0; r < 4; r++)
                a4[r] = *(const float4*)&A[rg * 4 + r][kk4 * 4];
#pragma unroll
            for (int qq = 0; qq < 4; qq++) {
                unsigned long long w = Wul[(kk4 * 4 + qq) * 64 + ch * 32 + lane];
#pragma unroll
                for (int r = 0; r < 4; r++) {
                    float av = (qq == 0) ? a4[r].x : (qq == 1) ? a4[r].y
                             : (qq == 2) ? a4[r].z : a4[r].w;
                    fma2(acc[r], dup2(av), w);
                }
            }
        }

        // store partials
#pragma unroll
        for (int r = 0; r < 4; r++) {
            int n = bx * 16 + rg * 4 + r;
            *(unsigned long long*)(g_P2[kz] + (size_t)n * 640 + g * 128 + ch * 64 + lane * 2)
                = acc[r];
        }

        grid_barrier(NB);

        // pointwise: 16384 elems spread over ALL 80 blocks (205 each)
        {
            int idx = bid * 205 + tid;
            if (tid < 205 && idx < 16384) {
                int n = idx >> 7, k = idx & 127;
                int mp0 = mapping[(lvl * 128 + n) * 2 + 0];
                int mp1 = mapping[(lvl * 128 + n) * 2 + 1];
                float lc = (mp0 > 0) ? g_c[p][(mp0 - 1) * 128 + k] : 0.f;
                float rc = (mp1 > 0) ? g_c[p][(mp1 - 1) * 128 + k] : 0.f;
                float bse = g_base[s * 128 + k];
                const float* P0 = g_P2[0] + (size_t)n * 640;
                const float* P1 = g_P2[1] + (size_t)n * 640;
                float pre[5];
#pragma unroll
                for (int qq = 0; qq < 5; qq++)
                    pre[qq] = bse + P0[qq * 128 + k] + P1[qq * 128 + k] + g_bb[qq * 128 + k];
                float ii = sigf(pre[0]), lf = sigf(pre[1]), rf = sigf(pre[2]);
                float u = tanh_(pre[3]), o = sigf(pre[4]);
                float c = ii * u + lf * lc + rf * rc;
                g_c[1 - p][n * 128 + k] = c;
                g_h[1 - p][n * 128 + k] = o * tanh_(c);
            }
        }

        grid_barrier(NB);
    }
}

// ---------------------------------------------------------------------------
// K5: fused tail: BN2 -> t1 -> BN3 -> t2 -> sigmoid output.  One block, 256.
// ---------------------------------------------------------------------------
__global__ void __launch_bounds__(256) tail_kernel(
    const float* __restrict__ g2, const float* __restrict__ be2,
    const float* __restrict__ Wt1, const float* __restrict__ bt1,
    const float* __restrict__ g3, const float* __restrict__ be3,
    const float* __restrict__ Wt2, const float* __restrict__ bt2,
    const float* __restrict__ Wo, const float* __restrict__ bo,
    float* __restrict__ out)
{
    __shared__ float t1s[128 * 64];  // 32KB
    __shared__ float sc[128], sh[128];
    __shared__ float red[256], red2[256];
    int tid = threadIdx.x;

    // BN2 stats over g_h[1] (128x128)
    {
        int col = tid & 127, part = tid >> 7;
        float s = 0.f, s2 = 0.f;
        for (int r = part; r < 128; r += 2) {
            float v = g_h[1][r * 128 + col];
            s += v; s2 += v * v;
        }
        red[tid] = s; red2[tid] = s2;
        __syncthreads();
        if (tid < 128) {
            s = red[tid] + red[tid + 128];
            s2 = red2[tid] + red2[tid + 128];
            float m = s * (1.f / 128.f);
            float v = s2 * (1.f / 128.f) - m * m;
            float scl = g2[tid] * rsqrtf(v + 1e-5f);
            sc[tid] = scl;
            sh[tid] = be2[tid] - m * scl;
        }
        __syncthreads();
    }

    // t1 = relu(bn2(h) @ Wt1 + bt1)  (128x64)
    for (int o = tid; o < 8192; o += 256) {
        int n = o >> 6, j = o & 63;
        float acc = bt1[j];
#pragma unroll 4
        for (int h = 0; h < 128; h++)
            acc += (g_h[1][n * 128 + h] * sc[h] + sh[h]) * Wt1[h * 64 + j];
        t1s[o] = fmaxf(acc, 0.f);
    }
    __syncthreads();

    // BN3 stats over t1s (128x64)
    {
        int col = tid & 63, part = tid >> 6;
        float s = 0.f, s2 = 0.f;
        for (int r = part; r < 128; r += 4) {
            float v = t1s[r * 64 + col];
            s += v; s2 += v * v;
        }
        red[tid] = s; red2[tid] = s2;
        __syncthreads();
        if (tid < 64) {
            for (int p = 1; p < 4; p++) { s += red[tid + 64 * p]; s2 += red2[tid + 64 * p]; }
            float m = s * (1.f / 128.f);
            float v = s2 * (1.f / 128.f) - m * m;
            float scl = g3[tid] * rsqrtf(v + 1e-5f);
            sc[tid] = scl;
            sh[tid] = be3[tid] - m * scl;
        }
        __syncthreads();
    }

    // t2 = relu(bn3(t1)@Wt2+bt2); out = sigmoid(t2@Wo+bo)
    if (tid < 128) {
        int n = tid;
        float tn[64];
#pragma unroll
        for (int i = 0; i < 64; i++) tn[i] = t1s[n * 64 + i] * sc[i] + sh[i];
        float a = bo[0];
        for (int j = 0; j < 64; j++) {
            float s = bt2[j];
#pragma unroll
            for (int i = 0; i < 64; i++) s += tn[i] * Wt2[i * 64 + j];
            a += fmaxf(s, 0.f) * Wo[j];
        }
        out[n] = sigf(a);
    }
}

// ---------------------------------------------------------------------------
extern "C" void kernel_launch(void* const* d_in, const int* in_sizes, int n_in,
                              void* d_out, int out_size)
{
    const float* operators = (const float*)d_in[0];
    const float* extra     = (const float*)d_in[1];
    const float* card      = (const float*)d_in[2];
    const float* cond1     = (const float*)d_in[3];
    const float* cond2     = (const float*)d_in[4];
    const int*   mapping   = (const int*)  d_in[5];
    const float* Wih1      = (const float*)d_in[6];
    const float* Whh1      = (const float*)d_in[7];
    const float* b1        = (const float*)d_in[8];
    const float* Wc        = (const float*)d_in[9];
    const float* bc        = (const float*)d_in[10];
    const float* g1        = (const float*)d_in[11];
    const float* be1       = (const float*)d_in[12];
    const float* Wih2      = (const float*)d_in[13];
    // d_in[14] = Whh2: unused (single step from zero state)
    const float* b2        = (const float*)d_in[15];
    const float* Win       = (const float*)d_in[16];
    const float* bin_      = (const float*)d_in[17];
    const float* Wlh       = (const float*)d_in[18];
    const float* blh       = (const float*)d_in[19];
    const float* Wrh       = (const float*)d_in[20];
    const float* brh       = (const float*)d_in[21];
    const float* g2        = (const float*)d_in[22];
    const float* be2       = (const float*)d_in[23];
    const float* Wt1       = (const float*)d_in[24];
    const float* bt1       = (const float*)d_in[25];
    const float* g3        = (const float*)d_in[26];
    const float* be3       = (const float*)d_in[27];
    const float* Wt2       = (const float*)d_in[28];
    const float* bt2       = (const float*)d_in[29];
    const float* Wo        = (const float*)d_in[30];
    const float* bo        = (const float*)d_in[31];
    float* out = (float*)d_out;

    const int LSTM1_SMEM = 50048 * 4;   // 200192 B
    const int TREE_SMEM  = 18496 * 4;   // 73984 B
    const int LO_SMEM    = 12800 * 4;   // 51200 B
    cudaFuncSetAttribute(lstm1_kernel,
                         cudaFuncAttributeMaxDynamicSharedMemorySize, LSTM1_SMEM);
    cudaFuncSetAttribute(tree_kernel,
                         cudaFuncAttributeMaxDynamicSharedMemorySize, TREE_SMEM);
    cudaFuncSetAttribute(lo_kernel,
                         cudaFuncAttributeMaxDynamicSharedMemorySize, LO_SMEM);

    // 5 launches; tree at our idx 3 so ncu (-s 5) profiles it.
    lstm1_kernel<<<148, 512, LSTM1_SMEM>>>(cond1, cond2, Wih1, Whh1, b1,
                                           Wlh, Wrh, blh, brh);
    lo_kernel<<<128, 256, LO_SMEM>>>(Wc, bc);
    prep_kernel<<<143, 128>>>(operators, extra, card, Wih2, b2, Win, bin_, g1, be1);
    tree_kernel<<<dim3(8, 5, 2), 256, TREE_SMEM>>>(mapping);
    tail_kernel<<<1, 256>>>(g2, be2, Wt1, bt1, g3, be3, Wt2, bt2, Wo, bo, out);
}